// round 4
// baseline (speedup 1.0000x reference)
#include <cuda_runtime.h>
#include <math.h>

#define T      4096
#define P      8
#define DM     256
#define DF     4096
#define DK     1024
#define NE     9

// ---------------- scratch (device globals; no allocations allowed) ----------
__device__ float    g_xlast[DF];
__device__ float    g_q[DK];
__device__ float    g_u[DF];
__device__ float    g_scores[T];
__device__ float    g_wtab[144];   // wo[72] | wd[72]  (unnormalized)
__device__ float    g_pc[DF];      // unnormalized att-weighted PE sum
__device__ float    g_ov[DK];
__device__ float    g_oacc[DK];
__device__ float    g_Z;
__device__ unsigned g_menc;        // ordered-uint encoding of running max score
__device__ int      g_io[T * P];
__device__ int      g_id[T * P];

#define LN1E4_OVER_2048 (9.210340371976184 / 2048.0)

__device__ __forceinline__ unsigned fenc(float f) {
    unsigned b = __float_as_uint(f);
    return (b & 0x80000000u) ? ~b : (b | 0x80000000u);
}
__device__ __forceinline__ float fdec(unsigned e) {
    unsigned b = (e & 0x80000000u) ? (e & 0x7fffffffu) : ~e;
    return __uint_as_float(b);
}

// ---------------- K1: prep = zero + one-hot index + x[T-1] -----------------
__global__ void k_prep(const int* __restrict__ obs,
                       const float* __restrict__ oe,
                       const float* __restrict__ de) {
    int i = blockIdx.x * blockDim.x + threadIdx.x;   // 0..32767 (t*P+p)
    const int* r0 = obs + (size_t)(2 * i) * NE;
    int io = 0, id = 0;
#pragma unroll
    for (int e = 0; e < NE; e++) {
        if (r0[e])      io = e;
        if (r0[NE + e]) id = e;
    }
    g_io[i] = io;
    g_id[i] = id;

    if (i < DF) {
        g_pc[i] = 0.f;
        if (i < DK) { g_q[i] = 0.f; g_ov[i] = 0.f; g_oacc[i] = 0.f; }
        if (i < 144) g_wtab[i] = 0.f;
        if (i == 0) { g_menc = 0u; g_Z = 0.f; }
        // x[T-1]
        int d = i;
        int p = d >> 9, r = d & 511;
        int row = 2 * ((T - 1) * P + p) + (r >= DM ? 1 : 0);
        const int* ro = obs + (size_t)row * NE;
        int idx = 0;
#pragma unroll
        for (int e = 0; e < NE; e++) if (ro[e]) idx = e;
        float ev = (r < DM) ? oe[idx * DM + r] : de[idx * DM + (r - DM)];
        int j = d >> 1;
        float fij = (float)exp(-(double)j * LN1E4_OVER_2048);
        float s, c;
        sincosf((float)(T - 1) * fij, &s, &c);
        g_xlast[d] = 16.0f * ev + ((d & 1) ? c : s);
    }
}

// ---------------- column matvec: y[k] += sum_d x[d]*W[d,k] (atomic) ---------
// blockDim = 256 (covers K=1024 as float4), CH rows per block, deep MLP.
template <int CH>
__global__ void __launch_bounds__(256) k_colmv(const float* __restrict__ W,
                                               const float* __restrict__ x,
                                               float* __restrict__ y) {
    int k4 = threadIdx.x;
    int d0 = blockIdx.x * CH;
    const float4* W4 = (const float4*)W;
    float4 w[CH];
#pragma unroll
    for (int i = 0; i < CH; i++)
        w[i] = __ldg(&W4[(size_t)(d0 + i) * 256 + k4]);
    float xv[CH];
#pragma unroll
    for (int i = 0; i < CH; i++) xv[i] = __ldg(&x[d0 + i]);
    float4 acc = make_float4(0.f, 0.f, 0.f, 0.f);
#pragma unroll
    for (int i = 0; i < CH; i++) {
        acc.x = fmaf(xv[i], w[i].x, acc.x);
        acc.y = fmaf(xv[i], w[i].y, acc.y);
        acc.z = fmaf(xv[i], w[i].z, acc.z);
        acc.w = fmaf(xv[i], w[i].w, acc.w);
    }
    atomicAdd(&y[4 * k4 + 0], acc.x);
    atomicAdd(&y[4 * k4 + 1], acc.y);
    atomicAdd(&y[4 * k4 + 2], acc.z);
    atomicAdd(&y[4 * k4 + 3], acc.w);
}

// ---------------- WV colmv with c built on the fly --------------------------
__global__ void __launch_bounds__(256) k_colmv_c(const float* __restrict__ W,
                                                 const float* __restrict__ oe,
                                                 const float* __restrict__ de,
                                                 float* __restrict__ y) {
    __shared__ float sh_x[16];
    int tid = threadIdx.x;
    int d0 = blockIdx.x * 16;
    if (tid < 16) {
        int d = d0 + tid;
        int p = d >> 9, r = d & 511;
        float a = 0.f;
        if (r < DM) {
#pragma unroll
            for (int e = 0; e < NE; e++) a = fmaf(g_wtab[p * 9 + e], __ldg(&oe[e * DM + r]), a);
        } else {
            int rr = r - DM;
#pragma unroll
            for (int e = 0; e < NE; e++) a = fmaf(g_wtab[72 + p * 9 + e], __ldg(&de[e * DM + rr]), a);
        }
        sh_x[tid] = 16.0f * a + g_pc[d];
    }
    __syncthreads();
    int k4 = tid;
    const float4* W4 = (const float4*)W;
    float4 w[16];
#pragma unroll
    for (int i = 0; i < 16; i++)
        w[i] = __ldg(&W4[(size_t)(d0 + i) * 256 + k4]);
    float4 acc = make_float4(0.f, 0.f, 0.f, 0.f);
#pragma unroll
    for (int i = 0; i < 16; i++) {
        float xv = sh_x[i];
        acc.x = fmaf(xv, w[i].x, acc.x);
        acc.y = fmaf(xv, w[i].y, acc.y);
        acc.z = fmaf(xv, w[i].z, acc.z);
        acc.w = fmaf(xv, w[i].w, acc.w);
    }
    atomicAdd(&y[4 * k4 + 0], acc.x);
    atomicAdd(&y[4 * k4 + 1], acc.y);
    atomicAdd(&y[4 * k4 + 2], acc.z);
    atomicAdd(&y[4 * k4 + 3], acc.w);
}

// ---------------- row matvec: u[row] = dot(WK[row,:], q), warp per row ------
__global__ void __launch_bounds__(256) k_rowmv(const float* __restrict__ W,
                                               const float* __restrict__ x,
                                               float* __restrict__ y) {
    __shared__ float4 sx[256];       // full q vector
    int tid = threadIdx.x;
    sx[tid] = ((const float4*)x)[tid];
    __syncthreads();
    int gw = (blockIdx.x * 256 + tid) >> 5;
    int lane = tid & 31;
    const float4* Wr = (const float4*)(W + (size_t)gw * DK);
    float4 w[8];
#pragma unroll
    for (int i = 0; i < 8; i++) w[i] = __ldg(&Wr[lane + 32 * i]);
    float acc = 0.f;
#pragma unroll
    for (int i = 0; i < 8; i++) {
        float4 v = sx[lane + 32 * i];
        acc = fmaf(w[i].x, v.x, acc);
        acc = fmaf(w[i].y, v.y, acc);
        acc = fmaf(w[i].z, v.z, acc);
        acc = fmaf(w[i].w, v.w, acc);
    }
#pragma unroll
    for (int o = 16; o; o >>= 1) acc += __shfl_xor_sync(0xffffffffu, acc, o);
    if (!lane) y[gw] = acc;
}

// ---------------- K4: scores (fused utab) + running max ---------------------
__global__ void k_scores(const float* __restrict__ oe, const float* __restrict__ de) {
    __shared__ float sh_tab[144];
    __shared__ float sh_peu[32];
    int tid = threadIdx.x;                // 256 threads
    int wid = tid >> 5, lane = tid & 31;
    // Phase A: per-block embedding-dot table (L2-resident operands)
    for (int ent = wid; ent < 144; ent += 8) {
        int kind = ent / 72;
        int p = (ent % 72) / 9;
        int e = ent % 9;
        const float4* e4 = (const float4*)((kind ? de : oe) + e * DM);
        const float4* u4 = (const float4*)(g_u + p * 512 + kind * DM);
        float acc = 0.f;
#pragma unroll
        for (int i = 0; i < 2; i++) {
            float4 a = __ldg(&e4[lane + 32 * i]);
            float4 b = u4[lane + 32 * i];
            acc += a.x * b.x + a.y * b.y + a.z * b.z + a.w * b.w;
        }
#pragma unroll
        for (int o = 16; o; o >>= 1) acc += __shfl_xor_sync(0xffffffffu, acc, o);
        if (!lane) sh_tab[ent] = acc;
    }
    if (tid < 32) sh_peu[tid] = 0.f;
    __syncthreads();

    int t0 = blockIdx.x * 32;             // 128 blocks
    float s[8], c[8], s1[8], c1[8], us[8], uc[8];
#pragma unroll
    for (int jj = 0; jj < 8; jj++) {
        int j = tid * 8 + jj;             // 0..2047
        float fij = (float)exp(-(double)j * LN1E4_OVER_2048);
        sincosf((float)t0 * fij, &s[jj], &c[jj]);
        sincosf(fij, &s1[jj], &c1[jj]);
        us[jj] = g_u[2 * j];
        uc[jj] = g_u[2 * j + 1];
    }
    for (int n = 0; n < 32; n++) {
        float part = 0.f;
#pragma unroll
        for (int jj = 0; jj < 8; jj++) part += us[jj] * s[jj] + uc[jj] * c[jj];
#pragma unroll
        for (int o = 16; o; o >>= 1) part += __shfl_xor_sync(0xffffffffu, part, o);
        if ((tid & 31) == 0) atomicAdd(&sh_peu[n], part);
#pragma unroll
        for (int jj = 0; jj < 8; jj++) {
            float ns = s[jj] * c1[jj] + c[jj] * s1[jj];
            float nc = c[jj] * c1[jj] - s[jj] * s1[jj];
            s[jj] = ns; c[jj] = nc;
        }
    }
    __syncthreads();
    if (tid < 32) {
        int t = t0 + tid;
        float es = 0.f;
#pragma unroll
        for (int p = 0; p < P; p++)
            es += sh_tab[p * 9 + g_io[t * P + p]] + sh_tab[72 + p * 9 + g_id[t * P + p]];
        float sc = 16.0f * es + sh_peu[tid];
        g_scores[t] = sc;
        float mx = sc;
#pragma unroll
        for (int o = 16; o; o >>= 1) mx = fmaxf(mx, __shfl_xor_sync(0xffffffffu, mx, o));
        if (tid == 0) atomicMax(&g_menc, fenc(mx));
    }
}

// ---------------- K5: pc + wtab + Z from unnormalized e_t -------------------
// blocks [0,512): pc (8 j-groups x 64 t-chunks); blocks [512,576): wtab+Z
__global__ void k_pcwtab() {
    int b = blockIdx.x;
    int tid = threadIdx.x;                // 256
    __shared__ float sh_e[64];
    __shared__ float sh_m;
    if (b < 512) {
        int jg = b & 7, ch = b >> 3;
        int t0 = ch * 64;
        if (tid == 0) sh_m = fdec(g_menc);
        __syncthreads();
        if (tid < 64) sh_e[tid] = __expf(g_scores[t0 + tid] * (1.0f / 32.0f) - sh_m);
        __syncthreads();
        int j = jg * 256 + tid;
        float fij = (float)exp(-(double)j * LN1E4_OVER_2048);
        float s, c, s1, c1;
        sincosf((float)t0 * fij, &s, &c);
        sincosf(fij, &s1, &c1);
        float as = 0.f, ac = 0.f;
        for (int n = 0; n < 64; n++) {
            float w = sh_e[n];
            as = fmaf(w, s, as);
            ac = fmaf(w, c, ac);
            float ns = fmaf(s, c1, c * s1);
            float nc = fmaf(c, c1, -s * s1);
            s = ns; c = nc;
        }
        atomicAdd(&g_pc[2 * j], as);
        atomicAdd(&g_pc[2 * j + 1], ac);
    } else {
        int ch = b - 512;                 // 0..63
        int t0 = ch * 64;
        __shared__ float sh[144];
        if (tid < 144) sh[tid] = 0.f;
        if (tid == 0) sh_m = fdec(g_menc);
        __syncthreads();
        if (tid < 64) sh_e[tid] = __expf(g_scores[t0 + tid] * (1.0f / 32.0f) - sh_m);
        __syncthreads();
        for (int k = tid; k < 512; k += 256) {   // 64 t x 8 p
            int tt = k >> 3, p = k & 7;
            int t = t0 + tt;
            float w = sh_e[tt];
            atomicAdd(&sh[p * 9 + g_io[t * P + p]], w);
            atomicAdd(&sh[72 + p * 9 + g_id[t * P + p]], w);
        }
        __syncthreads();
        if (tid < 144) atomicAdd(&g_wtab[tid], sh[tid]);
        if (tid == 192) {
            float z = 0.f;
#pragma unroll 8
            for (int n = 0; n < 64; n++) z += sh_e[n];
            atomicAdd(&g_Z, z);
        }
    }
}

// ---------------- K8: relu + policy/value heads (scaled by 1/Z) -------------
__global__ void k_logits(const float* __restrict__ Wo, const float* __restrict__ bo,
                         const float* __restrict__ Wd, const float* __restrict__ bd,
                         const float* __restrict__ Wv, const float* __restrict__ bv,
                         float* __restrict__ out, int out_size) {
    int o = blockIdx.x;                  // 129 blocks
    const float* Wr;
    float bias;
    if (o < 64)       { Wr = Wo + o * DK;        bias = bo[o]; }
    else if (o < 128) { Wr = Wd + (o - 64) * DK; bias = bd[o - 64]; }
    else              { Wr = Wv;                 bias = bv[0]; }
    int tid = threadIdx.x;               // 128 threads
    float acc = 0.f;
#pragma unroll 8
    for (int i = tid; i < DK; i += 128)
        acc += fmaxf(g_oacc[i], 0.f) * __ldg(&Wr[i]);
#pragma unroll
    for (int off = 16; off; off >>= 1) acc += __shfl_xor_sync(0xffffffffu, acc, off);
    __shared__ float sred[4];
    if ((tid & 31) == 0) sred[tid >> 5] = acc;
    __syncthreads();
    if (tid == 0 && o < out_size)
        out[o] = (sred[0] + sred[1] + sred[2] + sred[3]) * (1.0f / g_Z) + bias;
}

// ---------------- host launcher ---------------------------------------------
extern "C" void kernel_launch(void* const* d_in, const int* in_sizes, int n_in,
                              void* d_out, int out_size) {
    const int*   obs = (const int*)d_in[0];
    const float* oe  = (const float*)d_in[1];
    const float* de  = (const float*)d_in[2];
    const float* WQ  = (const float*)d_in[3];
    const float* WK  = (const float*)d_in[4];
    const float* WV  = (const float*)d_in[5];
    const float* WO  = (const float*)d_in[6];
    const float* Wo  = (const float*)d_in[7];
    const float* bo  = (const float*)d_in[8];
    const float* Wd  = (const float*)d_in[9];
    const float* bd  = (const float*)d_in[10];
    const float* Wv  = (const float*)d_in[11];
    const float* bv  = (const float*)d_in[12];
    float* out = (float*)d_out;

    float *p_xlast, *p_q, *p_u, *p_ov, *p_oacc;
    cudaGetSymbolAddress((void**)&p_xlast, g_xlast);
    cudaGetSymbolAddress((void**)&p_q, g_q);
    cudaGetSymbolAddress((void**)&p_u, g_u);
    cudaGetSymbolAddress((void**)&p_ov, g_ov);
    cudaGetSymbolAddress((void**)&p_oacc, g_oacc);

    k_prep<<<128, 256>>>(obs, oe, de);
    // q = xlast @ WQ   (4096 x 1024), 256 blocks x 16 rows
    k_colmv<16><<<256, 256>>>(WQ, p_xlast, p_q);
    // u = WK @ q       (4096 rows of length 1024)
    k_rowmv<<<512, 256>>>(WK, p_q, p_u);
    k_scores<<<128, 256>>>(oe, de);
    k_pcwtab<<<576, 256>>>();
    // ov = c @ WV      (c built on the fly from wtab/pc/emb)
    k_colmv_c<<<256, 256>>>(WV, oe, de, p_ov);
    // o_last = ov @ WO (1024 x 1024), 256 blocks x 4 rows
    k_colmv<4><<<256, 256>>>(WO, p_ov, p_oacc);
    k_logits<<<129, 128>>>(Wo, bo, Wd, bd, Wv, bv, out, out_size);
}

// round 5
// speedup vs baseline: 1.2995x; 1.2995x over previous
#include <cuda_runtime.h>
#include <math.h>

#define T      4096
#define P      8
#define DM     256
#define DF     4096
#define DK     1024
#define NE     9
#define NBLK   148
#define NTHR   256

// ---------------- scratch (device globals; no allocations allowed) ----------
__device__ float    g_xlast[DF];
__device__ float    g_q[DK];
__device__ float    g_u[DF];
__device__ float    g_fs1[2048];    // sin(fij)
__device__ float    g_fc1[2048];    // cos(fij)
__device__ float    g_scores[T];
__device__ float    g_wtab[144];    // wo[72] | wd[72]  (unnormalized)
__device__ float    g_pc[DF];       // unnormalized att-weighted PE sum -> becomes c
__device__ float    g_ov[DK];
__device__ float    g_oacc[DK];
__device__ float    g_Z;
__device__ unsigned g_menc;
__device__ unsigned g_bar;          // monotonic barrier counter (never reset)
__device__ int      g_io[T * P];
__device__ int      g_id[T * P];

#define LN1E4_OVER_2048 (9.210340371976184 / 2048.0)

__device__ __forceinline__ unsigned fenc(float f) {
    unsigned b = __float_as_uint(f);
    return (b & 0x80000000u) ? ~b : (b | 0x80000000u);
}
__device__ __forceinline__ float fdec(unsigned e) {
    unsigned b = (e & 0x80000000u) ? (e & 0x7fffffffu) : ~e;
    return __uint_as_float(b);
}

// grid-wide barrier: monotonic counter, safe across graph replays
__device__ __forceinline__ void gridbar() {
    __syncthreads();
    __threadfence();
    if (threadIdx.x == 0) {
        unsigned my = atomicAdd(&g_bar, 1u) + 1u;
        unsigned target = ((my + NBLK - 1u) / NBLK) * NBLK;
        unsigned cur;
        do {
            asm volatile("ld.acquire.gpu.u32 %0, [%1];" : "=r"(cur) : "l"(&g_bar) : "memory");
        } while ((int)(cur - target) < 0);
    }
    __syncthreads();
}

// sincos(n * theta) from sincos(theta) via binary composition; n < 4096, uniform.
__device__ __forceinline__ void rotpow12(float ps, float pc, unsigned n,
                                         float& so, float& co) {
    float s = 0.f, c = 1.f;
#pragma unroll
    for (int b = 0; b < 12; b++) {
        if (n & (1u << b)) {
            float t = fmaf(s, pc, c * ps);
            c = fmaf(c, pc, -s * ps);
            s = t;
        }
        float t2 = 2.f * ps * pc;
        pc = fmaf(pc, pc, -ps * ps);
        ps = t2;
    }
    so = s; co = c;
}

// column matvec y[k] += sum_d x[d]*W[d,k], K=1024, CH=8 rows/vb, prefetched.
__device__ __forceinline__ void colmv_phase(const float* __restrict__ W,
                                            const float* __restrict__ x,
                                            float* __restrict__ y, int nvb) {
    int tid = threadIdx.x;
    const float4* W4 = (const float4*)W;
    float4 acc = make_float4(0.f, 0.f, 0.f, 0.f);
    int vb = blockIdx.x;
    if (vb < nvb) {
        float4 w[8]; float xv[8];
#pragma unroll
        for (int i = 0; i < 8; i++) w[i] = __ldg(&W4[(size_t)(vb * 8 + i) * 256 + tid]);
#pragma unroll
        for (int i = 0; i < 8; i++) xv[i] = __ldg(&x[vb * 8 + i]);
        for (int nxt = vb + NBLK; ; nxt += NBLK) {
            float4 w2[8]; float xv2[8];
            bool more = nxt < nvb;
            if (more) {
#pragma unroll
                for (int i = 0; i < 8; i++) w2[i] = __ldg(&W4[(size_t)(nxt * 8 + i) * 256 + tid]);
#pragma unroll
                for (int i = 0; i < 8; i++) xv2[i] = __ldg(&x[nxt * 8 + i]);
            }
#pragma unroll
            for (int i = 0; i < 8; i++) {
                acc.x = fmaf(xv[i], w[i].x, acc.x);
                acc.y = fmaf(xv[i], w[i].y, acc.y);
                acc.z = fmaf(xv[i], w[i].z, acc.z);
                acc.w = fmaf(xv[i], w[i].w, acc.w);
            }
            if (!more) break;
#pragma unroll
            for (int i = 0; i < 8; i++) { w[i] = w2[i]; xv[i] = xv2[i]; }
        }
    }
    atomicAdd(&y[4 * tid + 0], acc.x);
    atomicAdd(&y[4 * tid + 1], acc.y);
    atomicAdd(&y[4 * tid + 2], acc.z);
    atomicAdd(&y[4 * tid + 3], acc.w);
}

__global__ void __launch_bounds__(NTHR, 1)
uber_kernel(const int* __restrict__ obs,
            const float* __restrict__ oe, const float* __restrict__ de,
            const float* __restrict__ WQ, const float* __restrict__ WK,
            const float* __restrict__ WV, const float* __restrict__ WO,
            const float* __restrict__ Wo, const float* __restrict__ bo,
            const float* __restrict__ Wd, const float* __restrict__ bd,
            const float* __restrict__ Wv, const float* __restrict__ bv,
            float* __restrict__ out, int out_size) {
    __shared__ float  sh_part[32 * NTHR];   // 32 KB
    __shared__ float  sh_tab[144];
    __shared__ float4 shq[256];
    __shared__ float  sh_e[32];
    __shared__ float  sh_red[8];

    int tid = threadIdx.x, bid = blockIdx.x;
    int wid = tid >> 5, lane = tid & 31;
    int g = bid * NTHR + tid;

    // ===== P0: tables + idx + zeros + xlast =================================
    if (g < 2048) {
        float fij = (float)exp(-(double)g * LN1E4_OVER_2048);
        float s1, c1; sincosf(fij, &s1, &c1);
        g_fs1[g] = s1; g_fc1[g] = c1;
    }
    if (g < T * P) {
        const int* r0 = obs + (size_t)(2 * g) * NE;
        int io = 0, id = 0;
#pragma unroll
        for (int e = 0; e < NE; e++) {
            if (r0[e])      io = e;
            if (r0[NE + e]) id = e;
        }
        g_io[g] = io; g_id[g] = id;
    }
    if (g < DF) {
        g_pc[g] = 0.f;
        if (g < DK) { g_q[g] = 0.f; g_ov[g] = 0.f; g_oacc[g] = 0.f; }
        if (g < 144) g_wtab[g] = 0.f;
        if (g == 0) { g_menc = 0u; g_Z = 0.f; }
        int d = g, p = d >> 9, r = d & 511;
        int row = 2 * ((T - 1) * P + p) + (r >= DM ? 1 : 0);
        const int* ro = obs + (size_t)row * NE;
        int idx = 0;
#pragma unroll
        for (int e = 0; e < NE; e++) if (ro[e]) idx = e;
        float ev = (r < DM) ? oe[idx * DM + r] : de[idx * DM + (r - DM)];
        int j = d >> 1;
        float fij = (float)exp(-(double)j * LN1E4_OVER_2048);
        float s1, c1; sincosf(fij, &s1, &c1);
        float s, c; rotpow12(s1, c1, T - 1, s, c);
        g_xlast[d] = 16.0f * ev + ((d & 1) ? c : s);
    }
    gridbar();

    // ===== P1: q = xlast @ WQ  (4096x1024) =================================
    colmv_phase(WQ, g_xlast, g_q, 512);
    gridbar();

    // ===== P2: u = WK @ q  (row dots), warp per row, prefetched ============
    shq[tid] = ((const float4*)g_q)[tid];
    __syncthreads();
    {
        int vb = bid;
        if (vb < 512) {
            const float4* Wr = (const float4*)(WK + (size_t)(vb * 8 + wid) * DK);
            float4 w[8];
#pragma unroll
            for (int i = 0; i < 8; i++) w[i] = __ldg(&Wr[lane + 32 * i]);
            for (int nxt = vb + NBLK; ; nxt += NBLK) {
                float4 w2[8];
                bool more = nxt < 512;
                if (more) {
                    const float4* Wr2 = (const float4*)(WK + (size_t)(nxt * 8 + wid) * DK);
#pragma unroll
                    for (int i = 0; i < 8; i++) w2[i] = __ldg(&Wr2[lane + 32 * i]);
                }
                float acc = 0.f;
#pragma unroll
                for (int i = 0; i < 8; i++) {
                    float4 v = shq[lane + 32 * i];
                    acc = fmaf(w[i].x, v.x, acc);
                    acc = fmaf(w[i].y, v.y, acc);
                    acc = fmaf(w[i].z, v.z, acc);
                    acc = fmaf(w[i].w, v.w, acc);
                }
#pragma unroll
                for (int o = 16; o; o >>= 1) acc += __shfl_xor_sync(0xffffffffu, acc, o);
                if (!lane) g_u[vb * 8 + wid] = acc;
                if (!more) break;
                vb = nxt;
#pragma unroll
                for (int i = 0; i < 8; i++) w[i] = w2[i];
            }
        }
    }
    gridbar();

    // ===== P3: utab + scores + running max =================================
    if (bid < 128) {
        for (int ent = wid; ent < 144; ent += 8) {
            int kind = ent / 72, p = (ent % 72) / 9, e = ent % 9;
            const float4* e4 = (const float4*)((kind ? de : oe) + e * DM);
            const float4* u4 = (const float4*)(g_u + p * 512 + kind * DM);
            float acc = 0.f;
#pragma unroll
            for (int i = 0; i < 2; i++) {
                float4 a = __ldg(&e4[lane + 32 * i]);
                float4 b = u4[lane + 32 * i];
                acc += a.x * b.x + a.y * b.y + a.z * b.z + a.w * b.w;
            }
#pragma unroll
            for (int o = 16; o; o >>= 1) acc += __shfl_xor_sync(0xffffffffu, acc, o);
            if (!lane) sh_tab[ent] = acc;
        }
        __syncthreads();

        int t0 = bid * 32;
        float s[8], c[8], s1v[8], c1v[8], us[8], uc[8];
#pragma unroll
        for (int jj = 0; jj < 8; jj++) {
            int j = tid + 256 * jj;
            float f1s = g_fs1[j], f1c = g_fc1[j];
            s1v[jj] = f1s; c1v[jj] = f1c;
            rotpow12(f1s, f1c, (unsigned)t0, s[jj], c[jj]);
            float2 u2 = ((const float2*)g_u)[j];
            us[jj] = u2.x; uc[jj] = u2.y;
        }
        for (int n = 0; n < 32; n++) {
            float part = 0.f;
#pragma unroll
            for (int jj = 0; jj < 8; jj++) {
                part = fmaf(us[jj], s[jj], part);
                part = fmaf(uc[jj], c[jj], part);
            }
            sh_part[n * NTHR + tid] = part;
#pragma unroll
            for (int jj = 0; jj < 8; jj++) {
                float ns = fmaf(s[jj], c1v[jj], c[jj] * s1v[jj]);
                float nc = fmaf(c[jj], c1v[jj], -s[jj] * s1v[jj]);
                s[jj] = ns; c[jj] = nc;
            }
        }
        __syncthreads();
#pragma unroll
        for (int rr = 0; rr < 4; rr++) {
            int r = wid * 4 + rr;
            float v = 0.f;
#pragma unroll
            for (int i = 0; i < 8; i++) v += sh_part[r * NTHR + lane + 32 * i];
#pragma unroll
            for (int o = 16; o; o >>= 1) v += __shfl_xor_sync(0xffffffffu, v, o);
            if (!lane) {
                int t = t0 + r;
                float es = 0.f;
#pragma unroll
                for (int p = 0; p < P; p++)
                    es += sh_tab[p * 9 + g_io[t * P + p]] + sh_tab[72 + p * 9 + g_id[t * P + p]];
                float sc = fmaf(16.0f, es, v);
                g_scores[t] = sc;
                atomicMax(&g_menc, fenc(sc));
            }
        }
    }
    gridbar();

    // ===== P4: e_t, wtab, Z, pc ============================================
    if (bid < 128) {
        int t0 = bid * 32;
        if (tid < 144) sh_tab[tid] = 0.f;
        if (tid < 32) {
            float m = fdec(g_menc);
            sh_e[tid] = __expf(fmaf(g_scores[t0 + tid], 1.0f / 32.0f, -m));
        }
        __syncthreads();
        {
            int tt = tid >> 3, p = tid & 7;
            int t = t0 + tt;
            float w = sh_e[tt];
            atomicAdd(&sh_tab[p * 9 + g_io[t * P + p]], w);
            atomicAdd(&sh_tab[72 + p * 9 + g_id[t * P + p]], w);
        }
        if (wid == 1) {
            float z = sh_e[lane];
#pragma unroll
            for (int o = 16; o; o >>= 1) z += __shfl_xor_sync(0xffffffffu, z, o);
            if (!lane) atomicAdd(&g_Z, z);
        }
#pragma unroll
        for (int jj = 0; jj < 8; jj++) {
            int j = tid + 256 * jj;
            float f1s = g_fs1[j], f1c = g_fc1[j];
            float s, c; rotpow12(f1s, f1c, (unsigned)t0, s, c);
            float as = 0.f, ac = 0.f;
            for (int n = 0; n < 32; n++) {
                float w = sh_e[n];
                as = fmaf(w, s, as);
                ac = fmaf(w, c, ac);
                float ns = fmaf(s, f1c, c * f1s);
                float nc = fmaf(c, f1c, -s * f1s);
                s = ns; c = nc;
            }
            atomicAdd(&g_pc[2 * j], as);
            atomicAdd(&g_pc[2 * j + 1], ac);
        }
        __syncthreads();
        if (tid < 144) atomicAdd(&g_wtab[tid], sh_tab[tid]);
    }
    gridbar();

    // ===== P5a: c[d] = 16*emb(wtab) + pc[d]  (in place into g_pc) ==========
    if (g < DF) {
        int d = g, p = d >> 9, r = d & 511;
        float a = 0.f;
        if (r < DM) {
#pragma unroll
            for (int e = 0; e < NE; e++) a = fmaf(g_wtab[p * 9 + e], __ldg(&oe[e * DM + r]), a);
        } else {
            int rr = r - DM;
#pragma unroll
            for (int e = 0; e < NE; e++) a = fmaf(g_wtab[72 + p * 9 + e], __ldg(&de[e * DM + rr]), a);
        }
        g_pc[d] = fmaf(16.0f, a, g_pc[d]);
    }
    gridbar();

    // ===== P5b: ov = c @ WV ================================================
    colmv_phase(WV, g_pc, g_ov, 512);
    gridbar();

    // ===== P6: oacc = ov @ WO ==============================================
    colmv_phase(WO, g_ov, g_oacc, 128);
    gridbar();

    // ===== P7: heads =======================================================
    if (bid < 129) {
        const float* Wr; float bias;
        if (bid < 64)       { Wr = Wo + bid * DK;        bias = bo[bid]; }
        else if (bid < 128) { Wr = Wd + (bid - 64) * DK; bias = bd[bid - 64]; }
        else                { Wr = Wv;                   bias = bv[0]; }
        float4 h4 = ((const float4*)g_oacc)[tid];
        float4 w4 = __ldg(&((const float4*)Wr)[tid]);
        float acc = fmaxf(h4.x, 0.f) * w4.x + fmaxf(h4.y, 0.f) * w4.y +
                    fmaxf(h4.z, 0.f) * w4.z + fmaxf(h4.w, 0.f) * w4.w;
#pragma unroll
        for (int o = 16; o; o >>= 1) acc += __shfl_xor_sync(0xffffffffu, acc, o);
        if (!lane) sh_red[wid] = acc;
        __syncthreads();
        if (tid == 0 && bid < out_size) {
            float sum = 0.f;
#pragma unroll
            for (int i = 0; i < 8; i++) sum += sh_red[i];
            out[bid] = sum * (1.0f / g_Z) + bias;
        }
    }
}

// ---------------- host launcher ---------------------------------------------
extern "C" void kernel_launch(void* const* d_in, const int* in_sizes, int n_in,
                              void* d_out, int out_size) {
    const int*   obs = (const int*)d_in[0];
    const float* oe  = (const float*)d_in[1];
    const float* de  = (const float*)d_in[2];
    const float* WQ  = (const float*)d_in[3];
    const float* WK  = (const float*)d_in[4];
    const float* WV  = (const float*)d_in[5];
    const float* WO  = (const float*)d_in[6];
    const float* Wo  = (const float*)d_in[7];
    const float* bo  = (const float*)d_in[8];
    const float* Wd  = (const float*)d_in[9];
    const float* bd  = (const float*)d_in[10];
    const float* Wv  = (const float*)d_in[11];
    const float* bv  = (const float*)d_in[12];
    float* out = (float*)d_out;

    uber_kernel<<<NBLK, NTHR>>>(obs, oe, de, WQ, WK, WV, WO,
                                Wo, bo, Wd, bd, Wv, bv, out, out_size);
}

// round 6
// speedup vs baseline: 1.3362x; 1.0282x over previous
#include <cuda_runtime.h>
#include <math.h>

#define T      4096
#define P      8
#define DM     256
#define DF     4096
#define DK     1024
#define NE     9
#define NBLK   148
#define NTHR   512

// ---------------- scratch (device globals; no allocations allowed) ----------
__device__ float    g_xlast[DF];
__device__ float    g_q[DK];
__device__ float    g_u[DF];
__device__ float    g_fs1[2048];
__device__ float    g_fc1[2048];
__device__ float    g_scores[T];
__device__ float    g_wtab[144];
__device__ float    g_pc[DF];       // att-weighted PE sum -> becomes c in place
__device__ float    g_ov[DK];
__device__ float    g_oacc[DK];
__device__ float    g_Z;
__device__ unsigned g_menc;
__device__ unsigned g_bar;          // monotonic barrier counter
__device__ int      g_io[T * P];
__device__ int      g_id[T * P];

#define LN1E4_OVER_2048 (9.210340371976184 / 2048.0)

__device__ __forceinline__ unsigned fenc(float f) {
    unsigned b = __float_as_uint(f);
    return (b & 0x80000000u) ? ~b : (b | 0x80000000u);
}
__device__ __forceinline__ float fdec(unsigned e) {
    unsigned b = (e & 0x80000000u) ? (e & 0x7fffffffu) : ~e;
    return __uint_as_float(b);
}

__device__ __forceinline__ void gridbar() {
    __syncthreads();
    __threadfence();
    if (threadIdx.x == 0) {
        unsigned my = atomicAdd(&g_bar, 1u) + 1u;
        unsigned target = ((my + NBLK - 1u) / NBLK) * NBLK;
        unsigned cur;
        for (;;) {
            asm volatile("ld.acquire.gpu.u32 %0, [%1];" : "=r"(cur) : "l"(&g_bar) : "memory");
            if ((int)(cur - target) >= 0) break;
            __nanosleep(64);
        }
    }
    __syncthreads();
}

// sincos(n*theta) by binary composition, n < 4096
__device__ __forceinline__ void rotpow12(float ps, float pc, unsigned n,
                                         float& so, float& co) {
    float s = 0.f, c = 1.f;
#pragma unroll
    for (int b = 0; b < 12; b++) {
        if (n & (1u << b)) {
            float t = fmaf(s, pc, c * ps);
            c = fmaf(c, pc, -s * ps);
            s = t;
        }
        float t2 = 2.f * ps * pc;
        pc = fmaf(pc, pc, -ps * ps);
        ps = t2;
    }
    so = s; co = c;
}

// colmv: y[k] += sum_d x[d]*W[d,k]; two 256-thread halves act as virtual CTAs.
// nvb counts 4-row chunks.
__device__ __forceinline__ void colmv512(const float* __restrict__ W,
                                         const float* __restrict__ x,
                                         float* __restrict__ y, int nvb,
                                         float* sh_acc) {
    int tid = threadIdx.x;
    int htid = tid & 255;
    int half = tid >> 8;
    const float4* W4 = (const float4*)W;
    float4 acc = make_float4(0.f, 0.f, 0.f, 0.f);
    int vb = blockIdx.x * 2 + half;       // 0..295
    if (vb < nvb) {
        float4 w[4]; float xv[4];
#pragma unroll
        for (int i = 0; i < 4; i++) w[i] = __ldg(&W4[(size_t)(vb * 4 + i) * 256 + htid]);
#pragma unroll
        for (int i = 0; i < 4; i++) xv[i] = __ldg(&x[vb * 4 + i]);
        for (int nxt = vb + 2 * NBLK; ; nxt += 2 * NBLK) {
            float4 w2[4]; float xv2[4];
            bool more = nxt < nvb;
            if (more) {
#pragma unroll
                for (int i = 0; i < 4; i++) w2[i] = __ldg(&W4[(size_t)(nxt * 4 + i) * 256 + htid]);
#pragma unroll
                for (int i = 0; i < 4; i++) xv2[i] = __ldg(&x[nxt * 4 + i]);
            }
#pragma unroll
            for (int i = 0; i < 4; i++) {
                acc.x = fmaf(xv[i], w[i].x, acc.x);
                acc.y = fmaf(xv[i], w[i].y, acc.y);
                acc.z = fmaf(xv[i], w[i].z, acc.z);
                acc.w = fmaf(xv[i], w[i].w, acc.w);
            }
            if (!more) break;
#pragma unroll
            for (int i = 0; i < 4; i++) { w[i] = w2[i]; xv[i] = xv2[i]; }
        }
    }
    if (half == 1) ((float4*)sh_acc)[htid] = acc;
    __syncthreads();
    if (half == 0) {
        float4 o = ((float4*)sh_acc)[htid];
        atomicAdd(&y[4 * htid + 0], acc.x + o.x);
        atomicAdd(&y[4 * htid + 1], acc.y + o.y);
        atomicAdd(&y[4 * htid + 2], acc.z + o.z);
        atomicAdd(&y[4 * htid + 3], acc.w + o.w);
    }
}

__global__ void __launch_bounds__(NTHR, 1)
uber_kernel(const int* __restrict__ obs,
            const float* __restrict__ oe, const float* __restrict__ de,
            const float* __restrict__ WQ, const float* __restrict__ WK,
            const float* __restrict__ WV, const float* __restrict__ WO,
            const float* __restrict__ Wo, const float* __restrict__ bo,
            const float* __restrict__ Wd, const float* __restrict__ bd,
            const float* __restrict__ Wv, const float* __restrict__ bv,
            float* __restrict__ out, int out_size) {
    __shared__ float  sh_part[32 * 256];    // 32 KB
    __shared__ float  sh_acc[DK];           // 4 KB
    __shared__ float  sh_tab[144];
    __shared__ float4 shq[256];
    __shared__ float  sh_e[32];
    __shared__ float  sh_red[16];

    int tid = threadIdx.x, bid = blockIdx.x;
    int wid = tid >> 5, lane = tid & 31;
    int half = tid >> 8, htid = tid & 255;
    int g = bid * NTHR + tid;

    // ===== P0: tables + idx + zeros + xlast =================================
    if (g < 2048) {
        float fij = (float)exp(-(double)g * LN1E4_OVER_2048);
        float s1, c1; sincosf(fij, &s1, &c1);
        g_fs1[g] = s1; g_fc1[g] = c1;
    }
    if (g < T * P) {
        const int* r0 = obs + (size_t)(2 * g) * NE;
        int io = 0, id = 0;
#pragma unroll
        for (int e = 0; e < NE; e++) {
            if (r0[e])      io = e;
            if (r0[NE + e]) id = e;
        }
        g_io[g] = io; g_id[g] = id;
    }
    if (g < DF) {
        g_pc[g] = 0.f;
        if (g < DK) { g_q[g] = 0.f; g_ov[g] = 0.f; g_oacc[g] = 0.f; }
        if (g < 144) g_wtab[g] = 0.f;
        if (g == 0) { g_menc = 0u; g_Z = 0.f; }
        int d = g, p = d >> 9, r = d & 511;
        int row = 2 * ((T - 1) * P + p) + (r >= DM ? 1 : 0);
        const int* ro = obs + (size_t)row * NE;
        int idx = 0;
#pragma unroll
        for (int e = 0; e < NE; e++) if (ro[e]) idx = e;
        float ev = (r < DM) ? oe[idx * DM + r] : de[idx * DM + (r - DM)];
        int j = d >> 1;
        float fij = (float)exp(-(double)j * LN1E4_OVER_2048);
        float s1, c1; sincosf(fij, &s1, &c1);
        float s, c; rotpow12(s1, c1, T - 1, s, c);
        g_xlast[d] = 16.0f * ev + ((d & 1) ? c : s);
    }
    gridbar();

    // ===== P1: q = xlast @ WQ  (4096 rows -> nvb=1024) ======================
    colmv512(WQ, g_xlast, g_q, 1024, sh_acc);
    gridbar();

    // ===== P2: u = WK @ q  (warp per row, 16 rows per vb) ==================
    if (tid < 256) shq[tid] = ((const float4*)g_q)[tid];
    __syncthreads();
    {
        int vb = bid;                       // nvb = 256
        if (vb < 256) {
            const float4* Wr = (const float4*)(WK + (size_t)(vb * 16 + wid) * DK);
            float4 w[8];
#pragma unroll
            for (int i = 0; i < 8; i++) w[i] = __ldg(&Wr[lane + 32 * i]);
            for (int nxt = vb + NBLK; ; nxt += NBLK) {
                float4 w2[8];
                bool more = nxt < 256;
                if (more) {
                    const float4* Wr2 = (const float4*)(WK + (size_t)(nxt * 16 + wid) * DK);
#pragma unroll
                    for (int i = 0; i < 8; i++) w2[i] = __ldg(&Wr2[lane + 32 * i]);
                }
                float acc = 0.f;
#pragma unroll
                for (int i = 0; i < 8; i++) {
                    float4 v = shq[lane + 32 * i];
                    acc = fmaf(w[i].x, v.x, acc);
                    acc = fmaf(w[i].y, v.y, acc);
                    acc = fmaf(w[i].z, v.z, acc);
                    acc = fmaf(w[i].w, v.w, acc);
                }
#pragma unroll
                for (int o = 16; o; o >>= 1) acc += __shfl_xor_sync(0xffffffffu, acc, o);
                if (!lane) g_u[vb * 16 + wid] = acc;
                if (!more) break;
                vb = nxt;
#pragma unroll
                for (int i = 0; i < 8; i++) w[i] = w2[i];
            }
        }
    }
    gridbar();

    // ===== P3: utab + scores + running max (two halves, 16 steps each) ======
    if (bid < 128) {
        for (int ent = wid; ent < 144; ent += 16) {
            int kind = ent / 72, p = (ent % 72) / 9, e = ent % 9;
            const float4* e4 = (const float4*)((kind ? de : oe) + e * DM);
            const float4* u4 = (const float4*)(g_u + p * 512 + kind * DM);
            float acc = 0.f;
#pragma unroll
            for (int i = 0; i < 2; i++) {
                float4 a = __ldg(&e4[lane + 32 * i]);
                float4 b = u4[lane + 32 * i];
                acc += a.x * b.x + a.y * b.y + a.z * b.z + a.w * b.w;
            }
#pragma unroll
            for (int o = 16; o; o >>= 1) acc += __shfl_xor_sync(0xffffffffu, acc, o);
            if (!lane) sh_tab[ent] = acc;
        }
        __syncthreads();

        int t0h = bid * 32 + half * 16;
        float s[8], c[8], s1v[8], c1v[8], us[8], uc[8];
#pragma unroll
        for (int jj = 0; jj < 8; jj++) {
            int j = htid + 256 * jj;
            float f1s = g_fs1[j], f1c = g_fc1[j];
            s1v[jj] = f1s; c1v[jj] = f1c;
            rotpow12(f1s, f1c, (unsigned)t0h, s[jj], c[jj]);
            float2 u2 = ((const float2*)g_u)[j];
            us[jj] = u2.x; uc[jj] = u2.y;
        }
        for (int n = 0; n < 16; n++) {
            float part = 0.f;
#pragma unroll
            for (int jj = 0; jj < 8; jj++) {
                part = fmaf(us[jj], s[jj], part);
                part = fmaf(uc[jj], c[jj], part);
            }
            sh_part[(half * 16 + n) * 256 + htid] = part;
#pragma unroll
            for (int jj = 0; jj < 8; jj++) {
                float ns = fmaf(s[jj], c1v[jj], c[jj] * s1v[jj]);
                float nc = fmaf(c[jj], c1v[jj], -s[jj] * s1v[jj]);
                s[jj] = ns; c[jj] = nc;
            }
        }
        __syncthreads();
#pragma unroll
        for (int rr = 0; rr < 2; rr++) {
            int r = wid * 2 + rr;           // 16 warps x 2 rows = 32
            float v = 0.f;
#pragma unroll
            for (int i = 0; i < 8; i++) v += sh_part[r * 256 + lane + 32 * i];
#pragma unroll
            for (int o = 16; o; o >>= 1) v += __shfl_xor_sync(0xffffffffu, v, o);
            if (!lane) {
                int t = bid * 32 + r;
                float es = 0.f;
#pragma unroll
                for (int p = 0; p < P; p++)
                    es += sh_tab[p * 9 + g_io[t * P + p]] + sh_tab[72 + p * 9 + g_id[t * P + p]];
                float sc = fmaf(16.0f, es, v);
                g_scores[t] = sc;
                atomicMax(&g_menc, fenc(sc));
            }
        }
    }
    gridbar();

    // ===== P4: e_t, wtab, Z, pc ============================================
    if (bid < 128) {
        int t0 = bid * 32;
        if (tid < 144) sh_tab[tid] = 0.f;
        if (tid >= 256 && tid < 288) {
            float m = fdec(g_menc);
            sh_e[tid - 256] = __expf(fmaf(g_scores[t0 + tid - 256], 1.0f / 32.0f, -m));
        }
        __syncthreads();
        if (tid < 256) {
            int tt = tid >> 3, p = tid & 7;
            int t = t0 + tt;
            float w = sh_e[tt];
            atomicAdd(&sh_tab[p * 9 + g_io[t * P + p]], w);
            atomicAdd(&sh_tab[72 + p * 9 + g_id[t * P + p]], w);
        }
        if (wid == 8) {
            float z = sh_e[lane];
#pragma unroll
            for (int o = 16; o; o >>= 1) z += __shfl_xor_sync(0xffffffffu, z, o);
            if (!lane) atomicAdd(&g_Z, z);
        }
#pragma unroll
        for (int jj = 0; jj < 4; jj++) {
            int j = tid + 512 * jj;
            float f1s = g_fs1[j], f1c = g_fc1[j];
            float s, c; rotpow12(f1s, f1c, (unsigned)t0, s, c);
            float as = 0.f, ac = 0.f;
#pragma unroll 4
            for (int n = 0; n < 32; n++) {
                float w = sh_e[n];
                as = fmaf(w, s, as);
                ac = fmaf(w, c, ac);
                float ns = fmaf(s, f1c, c * f1s);
                float nc = fmaf(c, f1c, -s * f1s);
                s = ns; c = nc;
            }
            atomicAdd(&g_pc[2 * j], as);
            atomicAdd(&g_pc[2 * j + 1], ac);
        }
        __syncthreads();
        if (tid < 144) atomicAdd(&g_wtab[tid], sh_tab[tid]);
    }
    gridbar();

    // ===== P5a: c[d] = 16*emb(wtab) + pc[d] (in place) ======================
    if (g < DF) {
        int d = g, p = d >> 9, r = d & 511;
        float a = 0.f;
        if (r < DM) {
#pragma unroll
            for (int e = 0; e < NE; e++) a = fmaf(g_wtab[p * 9 + e], __ldg(&oe[e * DM + r]), a);
        } else {
            int rr = r - DM;
#pragma unroll
            for (int e = 0; e < NE; e++) a = fmaf(g_wtab[72 + p * 9 + e], __ldg(&de[e * DM + rr]), a);
        }
        g_pc[d] = fmaf(16.0f, a, g_pc[d]);
    }
    gridbar();

    // ===== P5b: ov = c @ WV ================================================
    colmv512(WV, g_pc, g_ov, 1024, sh_acc);
    gridbar();

    // ===== P6: oacc = ov @ WO ==============================================
    colmv512(WO, g_ov, g_oacc, 256, sh_acc);
    gridbar();

    // ===== P7: heads =======================================================
    if (bid < 129) {
        const float* Wr; float bias;
        if (bid < 64)       { Wr = Wo + bid * DK;        bias = bo[bid]; }
        else if (bid < 128) { Wr = Wd + (bid - 64) * DK; bias = bd[bid - 64]; }
        else                { Wr = Wv;                   bias = bv[0]; }
        float acc = 0.f;
        if (tid < 256) {
            float4 h4 = ((const float4*)g_oacc)[tid];
            float4 w4 = __ldg(&((const float4*)Wr)[tid]);
            acc = fmaxf(h4.x, 0.f) * w4.x + fmaxf(h4.y, 0.f) * w4.y +
                  fmaxf(h4.z, 0.f) * w4.z + fmaxf(h4.w, 0.f) * w4.w;
        }
#pragma unroll
        for (int o = 16; o; o >>= 1) acc += __shfl_xor_sync(0xffffffffu, acc, o);
        if (!lane && wid < 8) sh_red[wid] = acc;
        __syncthreads();
        if (tid == 0 && bid < out_size) {
            float sum = 0.f;
#pragma unroll
            for (int i = 0; i < 8; i++) sum += sh_red[i];
            out[bid] = sum * (1.0f / g_Z) + bias;
        }
    }
}

// ---------------- host launcher ---------------------------------------------
extern "C" void kernel_launch(void* const* d_in, const int* in_sizes, int n_in,
                              void* d_out, int out_size) {
    const int*   obs = (const int*)d_in[0];
    const float* oe  = (const float*)d_in[1];
    const float* de  = (const float*)d_in[2];
    const float* WQ  = (const float*)d_in[3];
    const float* WK  = (const float*)d_in[4];
    const float* WV  = (const float*)d_in[5];
    const float* WO  = (const float*)d_in[6];
    const float* Wo  = (const float*)d_in[7];
    const float* bo  = (const float*)d_in[8];
    const float* Wd  = (const float*)d_in[9];
    const float* bd  = (const float*)d_in[10];
    const float* Wv  = (const float*)d_in[11];
    const float* bv  = (const float*)d_in[12];
    float* out = (float*)d_out;

    uber_kernel<<<NBLK, NTHR>>>(obs, oe, de, WQ, WK, WV, WO,
                                Wo, bo, Wd, bd, Wv, bv, out, out_size);
}